// round 10
// baseline (speedup 1.0000x reference)
#include <cuda_runtime.h>
#include <cstdint>

#define TT 1024
#define NB 128
#define ND 11              // poly degree 10 -> 11 terms, G is 11x11
#define BARBIG 0x40000000u

// ---- device scratch (static only) ----
__device__ float g_Hm[NB][128];
__device__ float g_H2[16][128];
__device__ float g_L[ND], g_R[ND];
__device__ float g_sc[NB], g_sc2[16];
__device__ unsigned g_cnt[2];

// Race-free grid barrier, 2 slots. Last arriver resets the OTHER slot
// FIRST, then releases via sentinel.
__device__ __forceinline__ void gbar(int p, int tid)
{
    __threadfence();
    __syncthreads();
    if (tid == 0) {
        unsigned old = atomicAdd(&g_cnt[p], 1u);
        if (old == NB - 1u) {
            g_cnt[p ^ 1] = 0u;
            __threadfence();
            atomicExch(&g_cnt[p], BARBIG);
        } else {
            while (*((volatile unsigned*)&g_cnt[p]) < BARBIG) { }
        }
    }
    __syncthreads();
}

__global__ __launch_bounds__(512) void mono_kernel(
    const float* __restrict__ obs,  const int* __restrict__ cids,
    const float* __restrict__ emb,
    const float* __restrict__ ecw,  const float* __restrict__ ecb,
    const float* __restrict__ elw,  const float* __restrict__ elb,
    const float* __restrict__ tcw,  const float* __restrict__ tcb,
    const float* __restrict__ tlw,  const float* __restrict__ tlb,
    float* __restrict__ out)
{
    extern __shared__ __align__(16) float dyn[];   // 2 x 16384 floats (128 KB)

    __shared__ __align__(16) float we0[256], we1[256], wt0[256], wt1[256];
    __shared__ float u_c[64], v_c[64], ek_c[64];
    __shared__ float od_s[9];
    __shared__ float Bt[ND][ND];
    __shared__ float red[16];
    __shared__ float s_ce, s_ct, s_mx;
    __shared__ float UP[64][12], VP[64][12];
    __shared__ float Wt[ND][64];
    __shared__ float Gb[9][128];
    __shared__ float Hp[2][128];
    __shared__ int   cid_s[576];
    __shared__ __align__(8) unsigned long long mbar[2];

    int tid  = threadIdx.x, b = blockIdx.x;
    int lane = tid & 31, w = tid >> 5;

    unsigned int dyn_base  = (unsigned int)__cvta_generic_to_shared(dyn);
    unsigned int mbar_base = (unsigned int)__cvta_generic_to_shared(mbar);

    //========== A: effective weights + scalar constants + mbarrier init ==========
    if (tid == 0) {
        asm volatile("mbarrier.init.shared::cta.b64 [%0], %1;" :: "r"(mbar_base),     "r"(1u));
        asm volatile("mbarrier.init.shared::cta.b64 [%0], %1;" :: "r"(mbar_base + 8u), "r"(1u));
    }
    if (tid < 256) {
        int d = tid;
        float em1 = (d > 0)   ? elw[d-1] : 0.f;
        float e0v = elw[d];
        float ep1 = (d < 255) ? elw[d+1] : 0.f;
        we0[d] = ecw[0]*ep1 + ecw[1]*e0v + ecw[2]*em1;
        we1[d] = ecw[3]*ep1 + ecw[4]*e0v + ecw[5]*em1;
        float tm1 = (d > 0)   ? tlw[d-1] : 0.f;
        float t0v = tlw[d];
        float tp1 = (d < 255) ? tlw[d+1] : 0.f;
        wt0[d] = tcw[0]*tp1 + tcw[1]*t0v + tcw[2]*tm1;
        wt1[d] = tcw[3]*tp1 + tcw[4]*t0v + tcw[5]*tm1;
        float ve = e0v, vt = t0v;
        #pragma unroll
        for (int o = 16; o; o >>= 1) {
            ve += __shfl_xor_sync(0xffffffffu, ve, o);
            vt += __shfl_xor_sync(0xffffffffu, vt, o);
        }
        if (lane == 0) { red[w] = ve; red[8 + w] = vt; }
    }
    __syncthreads();
    if (tid == 0) {
        float Se = 0.f, St = 0.f;
        #pragma unroll
        for (int i = 0; i < 8; i++) { Se += red[i]; St += red[8 + i]; }
        s_ce = ecb[0] * Se + elb[0];
        s_ct = tcb[0] * St + tlb[0];
    }
    __syncthreads();

    //========== B: Taylor coeffs of g(d)=exp(sigmoid(ct+d)), fp32 ==========
    if (tid == 0) {
        float p[12], q[12];
        float ct = s_ct;
        p[0] = 1.f / (1.f + expf(-ct));
        #pragma unroll
        for (int n = 0; n < 10; n++) {
            float acc = 0.f;
            for (int i = 0; i <= n; i++) acc += p[i] * p[n-i];
            p[n+1] = (p[n] - acc) / (float)(n + 1);
        }
        q[0] = expf(p[0]);
        #pragma unroll
        for (int n = 0; n < 10; n++) {
            float acc = 0.f;
            for (int i = 0; i <= n; i++) acc += (float)(i+1) * p[i+1] * q[n-i];
            q[n+1] = acc / (float)(n + 1);
        }
        float C[ND][ND];
        for (int n = 0; n < ND; n++) {
            C[n][0] = 1.f; C[n][n] = 1.f;
            for (int m = 1; m < n; m++) C[n][m] = C[n-1][m-1] + C[n-1][m];
        }
        for (int m = 0; m < ND; m++)
            for (int l = 0; l < ND; l++)
                Bt[m][l] = (m + l <= 10) ? q[m+l] * C[m+l][m] : 0.f;
    }

    //========== C: frame metadata ==========
    int f0  = 8 * b;
    int sLo = (b == 0)      ? 0 : 1;
    int sHi = (b == NB - 1) ? 7 : 8;
    int nf  = sHi - sLo + 1;

    for (int i = tid + sLo * 64; i < (sHi + 1) * 64; i += 512)
        cid_s[i] = __ldg(cids + f0 * 64 + i);

    if (w >= sLo && w <= sHi) {
        const float* op = obs + (size_t)(f0 + w) * 256;
        float od = 0.f;
        #pragma unroll
        for (int q8 = 0; q8 < 8; q8++)
            od += op[lane + 32*q8] * we0[lane + 32*q8];
        #pragma unroll
        for (int o = 16; o; o >>= 1) od += __shfl_xor_sync(0xffffffffu, od, o);
        if (lane == 0) od_s[w] = od;
    }
    __syncthreads();   // cid_s + weights + Bt + mbar init all visible

    // weight registers for the smem dot (lane-contiguous mapping)
    const float4* A4 = (const float4*)we1;
    const float4* B4 = (const float4*)wt0;
    const float4* C4 = (const float4*)wt1;
    float4 a_lo = A4[lane], a_hi = A4[32 + lane];
    float4 b_lo = B4[lane], b_hi = B4[32 + lane];
    float4 c_lo = C4[lane], c_hi = C4[32 + lane];

    // --- bulk-copy frame issue: one thread, 64 x 1KB rows, complete_tx ---
    auto issue_frame = [&](int fi) {
        if (tid == 0) {
            int s = sLo + fi;
            unsigned int mb  = mbar_base + (unsigned int)(fi & 1) * 8u;
            unsigned int dst = dyn_base  + (unsigned int)(fi & 1) * 65536u;
            asm volatile("mbarrier.arrive.expect_tx.shared::cta.b64 _, [%0], %1;"
                         :: "r"(mb), "r"(65536u) : "memory");
            const int* cs = &cid_s[s * 64];
            #pragma unroll 4
            for (int r = 0; r < 64; r++) {
                const float* src = emb + (size_t)cs[r] * 256;
                asm volatile(
                    "cp.async.bulk.shared::cta.global.mbarrier::complete_tx::bytes "
                    "[%0], [%1], %2, [%3];"
                    :: "r"(dst + (unsigned int)r * 1024u), "l"(src),
                       "r"(1024u), "r"(mb) : "memory");
            }
        }
    };
    auto wait_frame = [&](int fi) {
        unsigned int mb = mbar_base + (unsigned int)(fi & 1) * 8u;
        unsigned int ph = (unsigned int)((fi >> 1) & 1);
        asm volatile(
            "{\n\t.reg .pred P1;\n\t"
            "W%=:\n\t"
            "mbarrier.try_wait.parity.acquire.cta.shared::cta.b64 P1, [%0], %1, 0x989680;\n\t"
            "@P1 bra D%=;\n\t"
            "bra W%=;\n\t"
            "D%=:\n\t}"
            :: "r"(mb), "r"(ph) : "memory");
    };

    issue_frame(0);

    //========== fused frame loop: dots + per-slot G build ==========
    for (int fi = 0; fi < nf; fi++) {
        int s = sLo + fi;
        if (fi + 1 < nf) issue_frame(fi + 1);
        wait_frame(fi);

        const float4* bf = (const float4*)(dyn + (size_t)(fi & 1) * 16384);
        float ods = od_s[s], ce = s_ce;
        for (int rr = w; rr < 64; rr += 16) {    // warp per row
            float4 xl = bf[rr * 64 + lane];
            float4 xh = bf[rr * 64 + 32 + lane];
            float de = xl.x*a_lo.x + xl.y*a_lo.y + xl.z*a_lo.z + xl.w*a_lo.w
                     + xh.x*a_hi.x + xh.y*a_hi.y + xh.z*a_hi.z + xh.w*a_hi.w;
            float du = xl.x*b_lo.x + xl.y*b_lo.y + xl.z*b_lo.z + xl.w*b_lo.w
                     + xh.x*b_hi.x + xh.y*b_hi.y + xh.z*b_hi.z + xh.w*b_hi.w;
            float dv = xl.x*c_lo.x + xl.y*c_lo.y + xl.z*c_lo.z + xl.w*c_lo.w
                     + xh.x*c_hi.x + xh.y*c_hi.y + xh.z*c_hi.z + xh.w*c_hi.w;
            #pragma unroll
            for (int o = 16; o; o >>= 1) {
                de += __shfl_xor_sync(0xffffffffu, de, o);
                du += __shfl_xor_sync(0xffffffffu, du, o);
                dv += __shfl_xor_sync(0xffffffffu, dv, o);
            }
            if (lane == 0) {
                u_c[rr] = du;
                v_c[rr] = dv;
                float x  = de + ods + ce;
                float sg = __fdividef(1.f, 1.f + __expf(-x));
                ek_c[rr] = __expf(sg);
            }
        }
        __syncthreads();   // u_c/v_c/ek_c ready; dyn buffer reads done

        if (s >= 1) {
            // powers
            if (tid < 64) {
                float u = u_c[tid], pw = 1.f;
                UP[tid][0] = 1.f;
                #pragma unroll
                for (int l = 1; l <= 10; l++) { pw *= u; UP[tid][l] = pw; }
            } else if (tid < 128) {
                int k = tid - 64;
                float v = v_c[k], pw = 1.f;
                VP[k][0] = 1.f;
                #pragma unroll
                for (int l = 1; l <= 10; l++) { pw *= v; VP[k][l] = pw; }
            }
            __syncthreads();
            for (int e = tid; e < ND * 64; e += 512) {
                int m = e >> 6, k = e & 63;
                float acc = 0.f;
                #pragma unroll
                for (int l = 0; l < ND; l++) acc = fmaf(Bt[m][l], VP[k][l], acc);
                Wt[m][k] = acc * ek_c[k];
            }
            __syncthreads();
            bool isR = (b == NB - 1 && s == 7);
            if (!isR) {
                if (tid < 121) {
                    int m = tid / 11, l = tid - m * 11;
                    float acc = 0.f;
                    #pragma unroll 8
                    for (int k = 0; k < 64; k++)
                        acc = fmaf(Wt[m][k], UP[k][l], acc);
                    Gb[s][tid] = acc;
                }
            } else {
                if (tid < ND) {
                    float acc = 0.f;
                    for (int k = 0; k < 64; k++) acc += Wt[tid][k];
                    g_R[tid] = acc;
                }
            }
        } else if (b == 0) {
            // left boundary (frame 0): L[m] = sum_j ek0[j] * u0[j]^m
            if (tid < ND) {
                float acc = 0.f;
                for (int j = 0; j < 64; j++) {
                    float u = u_c[j], pw = 1.f;
                    for (int i = 0; i < tid; i++) pw *= u;
                    acc = fmaf(ek_c[j], pw, acc);
                }
                g_L[tid] = acc;
            }
        }
        __syncthreads();   // Wt/UP/VP/u_c free for next iteration
    }

    //========== E: fold this block's G chain ==========
    int ng = (b == NB - 1) ? 6 : 8;
    if (tid < 128) Hp[0][tid] = Gb[1][tid];
    __syncthreads();
    int cur = 0;
    for (int s = 2; s <= ng; s++) {
        if (tid < 121) {
            int m = tid / 11, l = tid - m * 11;
            float acc = 0.f;
            #pragma unroll
            for (int i = 0; i < ND; i++)
                acc = fmaf(Hp[cur][m*11 + i], Gb[s][i*11 + l], acc);
            Hp[cur ^ 1][tid] = acc;
        }
        cur ^= 1;
        __syncthreads();
    }
    {
        float vv = (tid < 121) ? fabsf(Hp[cur][tid]) : 0.f;
        #pragma unroll
        for (int o = 16; o; o >>= 1) vv = fmaxf(vv, __shfl_xor_sync(0xffffffffu, vv, o));
        if (lane == 0) red[w] = vv;
        __syncthreads();
        if (tid == 0) {
            float m = red[0];
            #pragma unroll
            for (int i = 1; i < 16; i++) m = fmaxf(m, red[i]);
            s_mx = m;
            g_sc[b] = logf(m);
        }
        __syncthreads();
        float inv = __fdividef(1.f, s_mx);
        if (tid < 121) g_Hm[b][tid] = Hp[cur][tid] * inv;
    }
    gbar(0, tid);

    //========== F: 16 blocks fold 8 H's each ==========
    if (b < 16) {
        if (tid < 121) Hp[0][tid] = __ldcg(&g_Hm[8*b][tid]);
        __syncthreads();
        int c2 = 0;
        for (int i = 1; i < 8; i++) {
            if (tid < 121) Gb[0][tid] = __ldcg(&g_Hm[8*b + i][tid]);
            __syncthreads();
            if (tid < 121) {
                int m = tid / 11, l = tid - m * 11;
                float acc = 0.f;
                #pragma unroll
                for (int q = 0; q < ND; q++)
                    acc = fmaf(Hp[c2][m*11 + q], Gb[0][q*11 + l], acc);
                Hp[c2 ^ 1][tid] = acc;
            }
            c2 ^= 1;
            __syncthreads();
        }
        float vv = (tid < 121) ? fabsf(Hp[c2][tid]) : 0.f;
        #pragma unroll
        for (int o = 16; o; o >>= 1) vv = fmaxf(vv, __shfl_xor_sync(0xffffffffu, vv, o));
        if (lane == 0) red[w] = vv;
        __syncthreads();
        if (tid == 0) {
            float m = red[0];
            #pragma unroll
            for (int i = 1; i < 16; i++) m = fmaxf(m, red[i]);
            s_mx = m;
            g_sc2[b] = logf(m);
        }
        __syncthreads();
        float inv = __fdividef(1.f, s_mx);
        if (tid < 121) g_H2[b][tid] = Hp[c2][tid] * inv;
    }
    gbar(1, tid);

    //========== G: block 0 folds 16, applies boundary vectors ==========
    if (b == 0) {
        if (tid < 121) Hp[0][tid] = __ldcg(&g_H2[0][tid]);
        __syncthreads();
        int c3 = 0;
        for (int i = 1; i < 16; i++) {
            if (tid < 121) Gb[0][tid] = __ldcg(&g_H2[i][tid]);
            __syncthreads();
            if (tid < 121) {
                int m = tid / 11, l = tid - m * 11;
                float acc = 0.f;
                #pragma unroll
                for (int q = 0; q < ND; q++)
                    acc = fmaf(Hp[c3][m*11 + q], Gb[0][q*11 + l], acc);
                Hp[c3 ^ 1][tid] = acc;
            }
            c3 ^= 1;
            __syncthreads();
        }
        float sv = (tid < NB) ? __ldcg(g_sc + tid) : 0.f;
        #pragma unroll
        for (int o = 16; o; o >>= 1) sv += __shfl_xor_sync(0xffffffffu, sv, o);
        if (lane == 0) red[w] = sv;
        __syncthreads();
        if (tid == 0) {
            float tot = red[0] + red[1] + red[2] + red[3];
            for (int i = 0; i < 16; i++) tot += g_sc2[i];
            float y[ND];
            for (int m = 0; m < ND; m++) {
                float acc = 0.f;
                for (int l = 0; l < ND; l++)
                    acc = fmaf(Hp[c3][m*11 + l], g_R[l], acc);
                y[m] = acc;
            }
            float z = 0.f;
            for (int m = 0; m < ND; m++) z = fmaf(g_L[m], y[m], z);
            out[0] = logf(z) + tot;
        }
    }
}

// ============================================================
extern "C" void kernel_launch(void* const* d_in, const int* in_sizes, int n_in,
                              void* d_out, int out_size)
{
    const float* obs = (const float*)d_in[0];
    const int*   cid = (const int*)  d_in[1];
    const float* emb = (const float*)d_in[2];
    const float* ecw = (const float*)d_in[3];
    const float* ecb = (const float*)d_in[4];
    const float* elw = (const float*)d_in[5];
    const float* elb = (const float*)d_in[6];
    const float* tcw = (const float*)d_in[7];
    const float* tcb = (const float*)d_in[8];
    const float* tlw = (const float*)d_in[9];
    const float* tlb = (const float*)d_in[10];
    float* out = (float*)d_out;

    static bool attr_set = false;
    if (!attr_set) {
        cudaFuncSetAttribute(mono_kernel,
                             cudaFuncAttributeMaxDynamicSharedMemorySize, 131072);
        attr_set = true;
    }

    mono_kernel<<<NB, 512, 131072>>>(obs, cid, emb, ecw, ecb, elw, elb,
                                     tcw, tcb, tlw, tlb, out);
}

// round 11
// speedup vs baseline: 1.1376x; 1.1376x over previous
#include <cuda_runtime.h>
#include <cstdint>

#define TT 1024
#define NB 128
#define ND 11              // poly degree 10 -> 11 terms, G is 11x11
#define BARBIG 0x40000000u
#define VMAX 100096

// ---- device scratch (static only) ----
__device__ float4  g_P4[VMAX];                 // vocab projection (de,du,dv,-)
__device__ unsigned g_used[(VMAX + 31) / 32];  // id bitmap (idempotent)
__device__ float g_Hm[NB][128];
__device__ float g_H2[16][128];
__device__ float g_L[ND], g_R[ND];
__device__ float g_sc[NB], g_sc2[16];
__device__ unsigned g_cnt[4];

// 4-slot grid barrier; phases run 0,1,2,3 per launch. Last arriver resets
// slot (p+2)&3 FIRST (not in use: it was consumed 2 phases ago / last replay),
// then releases via sentinel. Steady-state across graph replays verified.
__device__ __forceinline__ void gbar(int p, int tid)
{
    __threadfence();
    __syncthreads();
    if (tid == 0) {
        unsigned old = atomicAdd(&g_cnt[p], 1u);
        if (old == NB - 1u) {
            g_cnt[(p + 2) & 3] = 0u;
            __threadfence();
            atomicExch(&g_cnt[p], BARBIG);
        } else {
            while (*((volatile unsigned*)&g_cnt[p]) < BARBIG) { }
        }
    }
    __syncthreads();
}

__global__ __launch_bounds__(512) void mono_kernel(
    const float* __restrict__ obs,  const int* __restrict__ cids,
    const float* __restrict__ emb,
    const float* __restrict__ ecw,  const float* __restrict__ ecb,
    const float* __restrict__ elw,  const float* __restrict__ elb,
    const float* __restrict__ tcw,  const float* __restrict__ tcb,
    const float* __restrict__ tlw,  const float* __restrict__ tlb,
    float* __restrict__ out, int V)
{
    __shared__ __align__(16) float we0[256], we1[256], wt0[256], wt1[256];
    __shared__ float u_s[9][64], v_s[9][64], ek_s[9][64];
    __shared__ float od_s[9];
    __shared__ float Bt[ND][ND];
    __shared__ float red[16];
    __shared__ float s_ce, s_ct, s_mx;
    __shared__ float UP[64][12], VP[64][12];
    __shared__ float Wt[ND][64];
    __shared__ float Gb[9][128];
    __shared__ float Hp[2][128];
    __shared__ int   cid_s[576];

    int tid  = threadIdx.x, b = blockIdx.x;
    int lane = tid & 31, w = tid >> 5;

    //========== A: effective weights + scalar constants ==========
    if (tid < 256) {
        int d = tid;
        float em1 = (d > 0)   ? elw[d-1] : 0.f;
        float e0v = elw[d];
        float ep1 = (d < 255) ? elw[d+1] : 0.f;
        we0[d] = ecw[0]*ep1 + ecw[1]*e0v + ecw[2]*em1;
        we1[d] = ecw[3]*ep1 + ecw[4]*e0v + ecw[5]*em1;
        float tm1 = (d > 0)   ? tlw[d-1] : 0.f;
        float t0v = tlw[d];
        float tp1 = (d < 255) ? tlw[d+1] : 0.f;
        wt0[d] = tcw[0]*tp1 + tcw[1]*t0v + tcw[2]*tm1;
        wt1[d] = tcw[3]*tp1 + tcw[4]*t0v + tcw[5]*tm1;
        float ve = e0v, vt = t0v;
        #pragma unroll
        for (int o = 16; o; o >>= 1) {
            ve += __shfl_xor_sync(0xffffffffu, ve, o);
            vt += __shfl_xor_sync(0xffffffffu, vt, o);
        }
        if (lane == 0) { red[w] = ve; red[8 + w] = vt; }
    }
    __syncthreads();
    if (tid == 0) {
        float Se = 0.f, St = 0.f;
        #pragma unroll
        for (int i = 0; i < 8; i++) { Se += red[i]; St += red[8 + i]; }
        s_ce = ecb[0] * Se + elb[0];
        s_ct = tcb[0] * St + tlb[0];
    }

    //========== B: Taylor coeffs of g(d)=exp(sigmoid(ct+d)), fp32 ==========
    __syncthreads();
    if (tid == 0) {
        float p[12], q[12];
        float ct = s_ct;
        p[0] = 1.f / (1.f + expf(-ct));
        #pragma unroll
        for (int n = 0; n < 10; n++) {
            float acc = 0.f;
            for (int i = 0; i <= n; i++) acc += p[i] * p[n-i];
            p[n+1] = (p[n] - acc) / (float)(n + 1);
        }
        q[0] = expf(p[0]);
        #pragma unroll
        for (int n = 0; n < 10; n++) {
            float acc = 0.f;
            for (int i = 0; i <= n; i++) acc += (float)(i+1) * p[i+1] * q[n-i];
            q[n+1] = acc / (float)(n + 1);
        }
        float C[ND][ND];
        for (int n = 0; n < ND; n++) {
            C[n][0] = 1.f; C[n][n] = 1.f;
            for (int m = 1; m < n; m++) C[n][m] = C[n-1][m-1] + C[n-1][m];
        }
        for (int m = 0; m < ND; m++)
            for (int l = 0; l < ND; l++)
                Bt[m][l] = (m + l <= 10) ? q[m+l] * C[m+l][m] : 0.f;
    }

    //========== C0: cids + bitmap + obs dots ==========
    int f0  = 8 * b;
    int sLo = (b == 0)      ? 0 : 1;
    int sHi = (b == NB - 1) ? 7 : 8;
    int rbase0 = sLo * 64;
    int rend   = (sHi + 1) * 64;

    for (int i = tid + rbase0; i < rend; i += 512) {
        int c = __ldg(cids + f0 * 64 + i);
        cid_s[i] = c;
        atomicOr(&g_used[c >> 5], 1u << (c & 31));   // idempotent across replays
    }

    if (w >= sLo && w <= sHi) {
        const float* op = obs + (size_t)(f0 + w) * 256;
        float od = 0.f;
        #pragma unroll
        for (int q8 = 0; q8 < 8; q8++)
            od += op[lane + 32*q8] * we0[lane + 32*q8];
        #pragma unroll
        for (int o = 16; o; o >>= 1) od += __shfl_xor_sync(0xffffffffu, od, o);
        if (lane == 0) od_s[w] = od;
    }
    gbar(0, tid);    // all bits set chip-wide

    // weight registers (lane-contiguous float4 mapping)
    const float4* A4 = (const float4*)we1;
    const float4* B4 = (const float4*)wt0;
    const float4* C4 = (const float4*)wt1;
    float4 a_lo = A4[lane], a_hi = A4[32 + lane];
    float4 b_lo = B4[lane], b_hi = B4[32 + lane];
    float4 c_lo = C4[lane], c_hi = C4[32 + lane];

    //========== P: project used vocab rows (coalesced stream) ==========
    {
        int chunk = (V + NB - 1) / NB;
        int v0 = b * chunk;
        int vend = v0 + chunk; if (vend > V) vend = V;

        for (int vb = v0 + w * 4; vb < vend; vb += 64) {
            bool use[4];
            #pragma unroll
            for (int j = 0; j < 4; j++) {
                int v = vb + j;
                use[j] = (v < vend) &&
                         ((__ldcg(&g_used[v >> 5]) >> (v & 31)) & 1u);
            }
            float4 X[4][2];
            #pragma unroll
            for (int j = 0; j < 4; j++) if (use[j]) {
                const float4* e4 = (const float4*)(emb + (size_t)(vb + j) * 256);
                X[j][0] = __ldg(e4 + lane * 2);
                X[j][1] = __ldg(e4 + lane * 2 + 1);
            }
            float de[4], du[4], dv[4];
            #pragma unroll
            for (int j = 0; j < 4; j++) if (use[j]) {
                float4 p = X[j][0], q = X[j][1];
                de[j] = p.x*a_lo.x + p.y*a_lo.y + p.z*a_lo.z + p.w*a_lo.w
                      + q.x*a_hi.x + q.y*a_hi.y + q.z*a_hi.z + q.w*a_hi.w;
                du[j] = p.x*b_lo.x + p.y*b_lo.y + p.z*b_lo.z + p.w*b_lo.w
                      + q.x*b_hi.x + q.y*b_hi.y + q.z*b_hi.z + q.w*b_hi.w;
                dv[j] = p.x*c_lo.x + p.y*c_lo.y + p.z*c_lo.z + p.w*c_lo.w
                      + q.x*c_hi.x + q.y*c_hi.y + q.z*c_hi.z + q.w*c_hi.w;
            }
            #pragma unroll
            for (int j = 0; j < 4; j++) if (use[j]) {
                #pragma unroll
                for (int o = 16; o; o >>= 1) {
                    de[j] += __shfl_xor_sync(0xffffffffu, de[j], o);
                    du[j] += __shfl_xor_sync(0xffffffffu, du[j], o);
                    dv[j] += __shfl_xor_sync(0xffffffffu, dv[j], o);
                }
            }
            if (lane == 0) {
                #pragma unroll
                for (int j = 0; j < 4; j++) if (use[j])
                    g_P4[vb + j] = make_float4(de[j], du[j], dv[j], 0.f);
            }
        }
    }
    gbar(1, tid);    // P4 complete chip-wide

    //========== C1: tiny gather from P4 + ek transform ==========
    for (int i = tid + rbase0; i < rend; i += 512) {
        float4 p = __ldcg(&g_P4[cid_s[i]]);
        int s = i >> 6, r = i & 63;
        u_s[s][r] = p.y;
        v_s[s][r] = p.z;
        float x  = p.x + od_s[s] + s_ce;
        float sg = __fdividef(1.f, 1.f + __expf(-x));
        ek_s[s][r] = __expf(sg);
    }
    __syncthreads();

    //========== D: per frame slot -> 11x11 G (or R vector) ==========
    for (int s = 1; s <= sHi; s++) {
        if (tid < 64) {
            float u = u_s[s][tid], pw = 1.f;
            UP[tid][0] = 1.f;
            #pragma unroll
            for (int l = 1; l <= 10; l++) { pw *= u; UP[tid][l] = pw; }
        } else if (tid < 128) {
            int k = tid - 64;
            float v = v_s[s][k], pw = 1.f;
            VP[k][0] = 1.f;
            #pragma unroll
            for (int l = 1; l <= 10; l++) { pw *= v; VP[k][l] = pw; }
        }
        __syncthreads();
        for (int e = tid; e < ND * 64; e += 512) {
            int m = e >> 6, k = e & 63;
            float acc = 0.f;
            #pragma unroll
            for (int l = 0; l < ND; l++) acc = fmaf(Bt[m][l], VP[k][l], acc);
            Wt[m][k] = acc * ek_s[s][k];
        }
        __syncthreads();
        bool isR = (b == NB - 1 && s == 7);
        if (!isR) {
            if (tid < 121) {
                int m = tid / 11, l = tid - m * 11;
                float acc = 0.f;
                #pragma unroll 8
                for (int k = 0; k < 64; k++) acc = fmaf(Wt[m][k], UP[k][l], acc);
                Gb[s][tid] = acc;
            }
        } else {
            if (tid < ND) {
                float acc = 0.f;
                for (int k = 0; k < 64; k++) acc += Wt[tid][k];
                g_R[tid] = acc;
            }
        }
        __syncthreads();
    }
    if (b == 0 && tid < ND) {
        float acc = 0.f;
        for (int j = 0; j < 64; j++) {
            float u = u_s[0][j], pw = 1.f;
            for (int i = 0; i < tid; i++) pw *= u;
            acc = fmaf(ek_s[0][j], pw, acc);
        }
        g_L[tid] = acc;
    }

    //========== E: fold this block's G chain ==========
    int ng = (b == NB - 1) ? 6 : 8;
    if (tid < 128) Hp[0][tid] = Gb[1][tid];
    __syncthreads();
    int cur = 0;
    for (int s = 2; s <= ng; s++) {
        if (tid < 121) {
            int m = tid / 11, l = tid - m * 11;
            float acc = 0.f;
            #pragma unroll
            for (int i = 0; i < ND; i++)
                acc = fmaf(Hp[cur][m*11 + i], Gb[s][i*11 + l], acc);
            Hp[cur ^ 1][tid] = acc;
        }
        cur ^= 1;
        __syncthreads();
    }
    {
        float vv = (tid < 121) ? fabsf(Hp[cur][tid]) : 0.f;
        #pragma unroll
        for (int o = 16; o; o >>= 1) vv = fmaxf(vv, __shfl_xor_sync(0xffffffffu, vv, o));
        if (lane == 0) red[w] = vv;
        __syncthreads();
        if (tid == 0) {
            float m = red[0];
            #pragma unroll
            for (int i = 1; i < 16; i++) m = fmaxf(m, red[i]);
            s_mx = m;
            g_sc[b] = logf(m);
        }
        __syncthreads();
        float inv = __fdividef(1.f, s_mx);
        if (tid < 121) g_Hm[b][tid] = Hp[cur][tid] * inv;
    }
    gbar(2, tid);

    //========== F: 16 blocks fold 8 H's each ==========
    if (b < 16) {
        if (tid < 121) Hp[0][tid] = __ldcg(&g_Hm[8*b][tid]);
        __syncthreads();
        int c2 = 0;
        for (int i = 1; i < 8; i++) {
            if (tid < 121) Gb[0][tid] = __ldcg(&g_Hm[8*b + i][tid]);
            __syncthreads();
            if (tid < 121) {
                int m = tid / 11, l = tid - m * 11;
                float acc = 0.f;
                #pragma unroll
                for (int q = 0; q < ND; q++)
                    acc = fmaf(Hp[c2][m*11 + q], Gb[0][q*11 + l], acc);
                Hp[c2 ^ 1][tid] = acc;
            }
            c2 ^= 1;
            __syncthreads();
        }
        float vv = (tid < 121) ? fabsf(Hp[c2][tid]) : 0.f;
        #pragma unroll
        for (int o = 16; o; o >>= 1) vv = fmaxf(vv, __shfl_xor_sync(0xffffffffu, vv, o));
        if (lane == 0) red[w] = vv;
        __syncthreads();
        if (tid == 0) {
            float m = red[0];
            #pragma unroll
            for (int i = 1; i < 16; i++) m = fmaxf(m, red[i]);
            s_mx = m;
            g_sc2[b] = logf(m);
        }
        __syncthreads();
        float inv = __fdividef(1.f, s_mx);
        if (tid < 121) g_H2[b][tid] = Hp[c2][tid] * inv;
    }
    gbar(3, tid);

    //========== G: block 0 folds 16, applies boundary vectors ==========
    if (b == 0) {
        if (tid < 121) Hp[0][tid] = __ldcg(&g_H2[0][tid]);
        __syncthreads();
        int c3 = 0;
        for (int i = 1; i < 16; i++) {
            if (tid < 121) Gb[0][tid] = __ldcg(&g_H2[i][tid]);
            __syncthreads();
            if (tid < 121) {
                int m = tid / 11, l = tid - m * 11;
                float acc = 0.f;
                #pragma unroll
                for (int q = 0; q < ND; q++)
                    acc = fmaf(Hp[c3][m*11 + q], Gb[0][q*11 + l], acc);
                Hp[c3 ^ 1][tid] = acc;
            }
            c3 ^= 1;
            __syncthreads();
        }
        float sv = (tid < NB) ? __ldcg(g_sc + tid) : 0.f;
        #pragma unroll
        for (int o = 16; o; o >>= 1) sv += __shfl_xor_sync(0xffffffffu, sv, o);
        if (lane == 0) red[w] = sv;
        __syncthreads();
        if (tid == 0) {
            float tot = red[0] + red[1] + red[2] + red[3];
            for (int i = 0; i < 16; i++) tot += g_sc2[i];
            float y[ND];
            for (int m = 0; m < ND; m++) {
                float acc = 0.f;
                for (int l = 0; l < ND; l++)
                    acc = fmaf(Hp[c3][m*11 + l], g_R[l], acc);
                y[m] = acc;
            }
            float z = 0.f;
            for (int m = 0; m < ND; m++) z = fmaf(g_L[m], y[m], z);
            out[0] = logf(z) + tot;
        }
    }
}

// ============================================================
extern "C" void kernel_launch(void* const* d_in, const int* in_sizes, int n_in,
                              void* d_out, int out_size)
{
    const float* obs = (const float*)d_in[0];
    const int*   cid = (const int*)  d_in[1];
    const float* emb = (const float*)d_in[2];
    const float* ecw = (const float*)d_in[3];
    const float* ecb = (const float*)d_in[4];
    const float* elw = (const float*)d_in[5];
    const float* elb = (const float*)d_in[6];
    const float* tcw = (const float*)d_in[7];
    const float* tcb = (const float*)d_in[8];
    const float* tlw = (const float*)d_in[9];
    const float* tlb = (const float*)d_in[10];
    float* out = (float*)d_out;
    int V = in_sizes[2] / 256;         // vocab size from embedding tensor

    mono_kernel<<<NB, 512>>>(obs, cid, emb, ecw, ecb, elw, elb,
                             tcw, tcb, tlw, tlb, out, V);
}

// round 12
// speedup vs baseline: 1.5991x; 1.4057x over previous
#include <cuda_runtime.h>
#include <cstdint>

#define TT 1024
#define NB 128
#define ND 11              // poly degree 10 -> 11 terms, G is 11x11
#define BARBIG 0x40000000u

// ---- device scratch (static only) ----
__device__ float g_Hm[NB][128];
__device__ float g_H2[16][128];
__device__ float g_L[ND], g_R[ND];
__device__ float g_sc[NB], g_sc2[16];
__device__ unsigned g_cnt[2];

// Race-free grid barrier, 2 slots (proven R7/R9). Last arriver resets the
// OTHER slot FIRST, then releases via sentinel.
__device__ __forceinline__ void gbar(int p, int tid)
{
    __threadfence();
    __syncthreads();
    if (tid == 0) {
        unsigned old = atomicAdd(&g_cnt[p], 1u);
        if (old == NB - 1u) {
            g_cnt[p ^ 1] = 0u;
            __threadfence();
            atomicExch(&g_cnt[p], BARBIG);
        } else {
            while (*((volatile unsigned*)&g_cnt[p]) < BARBIG) { }
        }
    }
    __syncthreads();
}

__global__ __launch_bounds__(512) void mono_kernel(
    const float* __restrict__ obs,  const int* __restrict__ cids,
    const float* __restrict__ emb,
    const float* __restrict__ ecw,  const float* __restrict__ ecb,
    const float* __restrict__ elw,  const float* __restrict__ elb,
    const float* __restrict__ tcw,  const float* __restrict__ tcb,
    const float* __restrict__ tlw,  const float* __restrict__ tlb,
    float* __restrict__ out)
{
    __shared__ __align__(16) float we0[256], we1[256], wt0[256], wt1[256];
    __shared__ float part[6336];           // [row*3+dot][33] per-lane partials
    __shared__ float u_c[64], v_c[64], ek_c[64];
    __shared__ float od_s[9];
    __shared__ float Bt[ND][ND];
    __shared__ float red[16];
    __shared__ float s_ce, s_ct, s_mx;
    __shared__ float UP[64][11], VP[64][11];
    __shared__ float Wt[ND][64];
    __shared__ float Gb[9][121];
    __shared__ float Hp[2][128];
    __shared__ int   cid_s[576];

    int tid  = threadIdx.x, b = blockIdx.x;
    int lane = tid & 31, w = tid >> 5;

    //========== A: effective weights + scalar constants ==========
    if (tid < 256) {
        int d = tid;
        float em1 = (d > 0)   ? elw[d-1] : 0.f;
        float e0v = elw[d];
        float ep1 = (d < 255) ? elw[d+1] : 0.f;
        we0[d] = ecw[0]*ep1 + ecw[1]*e0v + ecw[2]*em1;
        we1[d] = ecw[3]*ep1 + ecw[4]*e0v + ecw[5]*em1;
        float tm1 = (d > 0)   ? tlw[d-1] : 0.f;
        float t0v = tlw[d];
        float tp1 = (d < 255) ? tlw[d+1] : 0.f;
        wt0[d] = tcw[0]*tp1 + tcw[1]*t0v + tcw[2]*tm1;
        wt1[d] = tcw[3]*tp1 + tcw[4]*t0v + tcw[5]*tm1;
        float ve = e0v, vt = t0v;
        #pragma unroll
        for (int o = 16; o; o >>= 1) {
            ve += __shfl_xor_sync(0xffffffffu, ve, o);
            vt += __shfl_xor_sync(0xffffffffu, vt, o);
        }
        if (lane == 0) { red[w] = ve; red[8 + w] = vt; }
    }
    __syncthreads();
    if (tid == 0) {
        float Se = 0.f, St = 0.f;
        #pragma unroll
        for (int i = 0; i < 8; i++) { Se += red[i]; St += red[8 + i]; }
        s_ce = ecb[0] * Se + elb[0];
        s_ct = tcb[0] * St + tlb[0];
    }
    __syncthreads();

    //========== B: Taylor coeffs of g(d)=exp(sigmoid(ct+d)), fp32 ==========
    if (tid == 0) {
        float p[12], q[12];
        float ct = s_ct;
        p[0] = 1.f / (1.f + expf(-ct));
        #pragma unroll
        for (int n = 0; n < 10; n++) {
            float acc = 0.f;
            for (int i = 0; i <= n; i++) acc += p[i] * p[n-i];
            p[n+1] = (p[n] - acc) / (float)(n + 1);
        }
        q[0] = expf(p[0]);
        #pragma unroll
        for (int n = 0; n < 10; n++) {
            float acc = 0.f;
            for (int i = 0; i <= n; i++) acc += (float)(i+1) * p[i+1] * q[n-i];
            q[n+1] = acc / (float)(n + 1);
        }
        float C[ND][ND];
        for (int n = 0; n < ND; n++) {
            C[n][0] = 1.f; C[n][n] = 1.f;
            for (int m = 1; m < n; m++) C[n][m] = C[n-1][m-1] + C[n-1][m];
        }
        for (int m = 0; m < ND; m++)
            for (int l = 0; l < ND; l++)
                Bt[m][l] = (m + l <= 10) ? q[m+l] * C[m+l][m] : 0.f;
    }

    //========== C0: cids + obs dots ==========
    int f0  = 8 * b;
    int sLo = (b == 0)      ? 0 : 1;
    int sHi = (b == NB - 1) ? 7 : 8;
    int nf  = sHi - sLo + 1;

    for (int i = tid + sLo * 64; i < (sHi + 1) * 64; i += 512)
        cid_s[i] = __ldg(cids + f0 * 64 + i);

    if (w >= sLo && w <= sHi) {
        const float* op = obs + (size_t)(f0 + w) * 256;
        float od = 0.f;
        #pragma unroll
        for (int q8 = 0; q8 < 8; q8++)
            od += op[lane + 32*q8] * we0[lane + 32*q8];
        #pragma unroll
        for (int o = 16; o; o >>= 1) od += __shfl_xor_sync(0xffffffffu, od, o);
        if (lane == 0) od_s[w] = od;
    }
    __syncthreads();   // cid_s + weights + Bt all visible

    // weight registers (lane-contiguous float4 mapping: floats 4l..4l+3, 128+4l..)
    const float4* A4 = (const float4*)we1;
    const float4* B4 = (const float4*)wt0;
    const float4* C4 = (const float4*)wt1;
    float4 a_lo = A4[lane], a_hi = A4[32 + lane];
    float4 b_lo = B4[lane], b_hi = B4[32 + lane];
    float4 c_lo = C4[lane], c_hi = C4[32 + lane];

    float4 X[4][2];    // prefetch buffer: warp's 4 rows of current frame
    auto load_frame = [&](int s) {
        #pragma unroll
        for (int r = 0; r < 4; r++) {
            const float4* e4 =
                (const float4*)(emb + (size_t)cid_s[s * 64 + 4 * w + r] * 256);
            X[r][0] = __ldg(e4 + lane);
            X[r][1] = __ldg(e4 + 32 + lane);
        }
    };

    load_frame(sLo);

    //========== fused frame loop: partial dots (no shfl) + reduce + G build ==========
    for (int fi = 0; fi < nf; fi++) {
        int s = sLo + fi;

        // 1) per-lane partial dots, pure FMA, consume X
        float de[4], du[4], dv[4];
        #pragma unroll
        for (int r = 0; r < 4; r++) {
            float4 p = X[r][0], q = X[r][1];
            de[r] = p.x*a_lo.x + p.y*a_lo.y + p.z*a_lo.z + p.w*a_lo.w
                  + q.x*a_hi.x + q.y*a_hi.y + q.z*a_hi.z + q.w*a_hi.w;
            du[r] = p.x*b_lo.x + p.y*b_lo.y + p.z*b_lo.z + p.w*b_lo.w
                  + q.x*b_hi.x + q.y*b_hi.y + q.z*b_hi.z + q.w*b_hi.w;
            dv[r] = p.x*c_lo.x + p.y*c_lo.y + p.z*c_lo.z + p.w*c_lo.w
                  + q.x*c_hi.x + q.y*c_hi.y + q.z*c_hi.z + q.w*c_hi.w;
        }
        // 2) conflict-free STS of partials
        #pragma unroll
        for (int r = 0; r < 4; r++) {
            float* pp = &part[((4 * w + r) * 3) * 33 + lane];
            pp[0]  = de[r];
            pp[33] = du[r];
            pp[66] = dv[r];
        }
        // 3) prefetch next frame (overlaps reduce + D below)
        if (fi + 1 < nf) load_frame(s + 1);
        __syncthreads();

        // 4) reduce 32 partials per (row,dot) — independent scalar LDS, no chains
        if (tid < 192) {
            int row = tid / 3, dot = tid - row * 3;
            const float* pp = &part[tid * 33];
            float s0 = 0.f, s1 = 0.f, s2 = 0.f, s3 = 0.f;
            #pragma unroll
            for (int q = 0; q < 32; q += 4) {
                s0 += pp[q]; s1 += pp[q+1]; s2 += pp[q+2]; s3 += pp[q+3];
            }
            float sum = (s0 + s1) + (s2 + s3);
            if (dot == 0) {
                float x  = sum + od_s[s] + s_ce;
                float sg = __fdividef(1.f, 1.f + __expf(-x));
                ek_c[row] = __expf(sg);
            } else if (dot == 1) u_c[row] = sum;
            else                 v_c[row] = sum;
        }
        __syncthreads();

        // 5) per-frame G build (rank-11)
        if (s >= 1) {
            if (tid < 64) {
                float u = u_c[tid], pw = 1.f;
                UP[tid][0] = 1.f;
                #pragma unroll
                for (int l = 1; l <= 10; l++) { pw *= u; UP[tid][l] = pw; }
            } else if (tid < 128) {
                int k = tid - 64;
                float v = v_c[k], pw = 1.f;
                VP[k][0] = 1.f;
                #pragma unroll
                for (int l = 1; l <= 10; l++) { pw *= v; VP[k][l] = pw; }
            }
            __syncthreads();
            for (int e = tid; e < ND * 64; e += 512) {
                int m = e >> 6, k = e & 63;
                float acc = 0.f;
                #pragma unroll
                for (int l = 0; l < ND; l++) acc = fmaf(Bt[m][l], VP[k][l], acc);
                Wt[m][k] = acc * ek_c[k];
            }
            __syncthreads();
            bool isR = (b == NB - 1 && s == 7);
            if (!isR) {
                if (tid < 121) {
                    int m = tid / 11, l = tid - m * 11;
                    float acc = 0.f;
                    #pragma unroll 8
                    for (int k = 0; k < 64; k++)
                        acc = fmaf(Wt[m][k], UP[k][l], acc);
                    Gb[s][tid] = acc;
                }
            } else {
                if (tid < ND) {
                    float acc = 0.f;
                    for (int k = 0; k < 64; k++) acc += Wt[tid][k];
                    g_R[tid] = acc;
                }
            }
        } else if (b == 0) {
            if (tid < ND) {
                float acc = 0.f;
                for (int j = 0; j < 64; j++) {
                    float u = u_c[j], pw = 1.f;
                    for (int i = 0; i < tid; i++) pw *= u;
                    acc = fmaf(ek_c[j], pw, acc);
                }
                g_L[tid] = acc;
            }
        }
        __syncthreads();   // UP/VP/Wt/u_c free; part reusable next iteration
    }

    //========== E: fold this block's G chain ==========
    int ng = (b == NB - 1) ? 6 : 8;
    if (tid < 121) Hp[0][tid] = Gb[1][tid];
    __syncthreads();
    int cur = 0;
    for (int s = 2; s <= ng; s++) {
        if (tid < 121) {
            int m = tid / 11, l = tid - m * 11;
            float acc = 0.f;
            #pragma unroll
            for (int i = 0; i < ND; i++)
                acc = fmaf(Hp[cur][m*11 + i], Gb[s][i*11 + l], acc);
            Hp[cur ^ 1][tid] = acc;
        }
        cur ^= 1;
        __syncthreads();
    }
    {
        float vv = (tid < 121) ? fabsf(Hp[cur][tid]) : 0.f;
        #pragma unroll
        for (int o = 16; o; o >>= 1) vv = fmaxf(vv, __shfl_xor_sync(0xffffffffu, vv, o));
        if (lane == 0) red[w] = vv;
        __syncthreads();
        if (tid == 0) {
            float m = red[0];
            #pragma unroll
            for (int i = 1; i < 16; i++) m = fmaxf(m, red[i]);
            s_mx = m;
            g_sc[b] = logf(m);
        }
        __syncthreads();
        float inv = __fdividef(1.f, s_mx);
        if (tid < 121) g_Hm[b][tid] = Hp[cur][tid] * inv;
    }
    gbar(0, tid);

    //========== F: 16 blocks fold 8 H's each ==========
    if (b < 16) {
        if (tid < 121) Hp[0][tid] = __ldcg(&g_Hm[8*b][tid]);
        __syncthreads();
        int c2 = 0;
        for (int i = 1; i < 8; i++) {
            if (tid < 121) part[tid] = __ldcg(&g_Hm[8*b + i][tid]);
            __syncthreads();
            if (tid < 121) {
                int m = tid / 11, l = tid - m * 11;
                float acc = 0.f;
                #pragma unroll
                for (int q = 0; q < ND; q++)
                    acc = fmaf(Hp[c2][m*11 + q], part[q*11 + l], acc);
                Hp[c2 ^ 1][tid] = acc;
            }
            c2 ^= 1;
            __syncthreads();
        }
        float vv = (tid < 121) ? fabsf(Hp[c2][tid]) : 0.f;
        #pragma unroll
        for (int o = 16; o; o >>= 1) vv = fmaxf(vv, __shfl_xor_sync(0xffffffffu, vv, o));
        if (lane == 0) red[w] = vv;
        __syncthreads();
        if (tid == 0) {
            float m = red[0];
            #pragma unroll
            for (int i = 1; i < 16; i++) m = fmaxf(m, red[i]);
            s_mx = m;
            g_sc2[b] = logf(m);
        }
        __syncthreads();
        float inv = __fdividef(1.f, s_mx);
        if (tid < 121) g_H2[b][tid] = Hp[c2][tid] * inv;
    }
    gbar(1, tid);

    //========== G: block 0 folds 16, applies boundary vectors ==========
    if (b == 0) {
        if (tid < 121) Hp[0][tid] = __ldcg(&g_H2[0][tid]);
        __syncthreads();
        int c3 = 0;
        for (int i = 1; i < 16; i++) {
            if (tid < 121) part[tid] = __ldcg(&g_H2[i][tid]);
            __syncthreads();
            if (tid < 121) {
                int m = tid / 11, l = tid - m * 11;
                float acc = 0.f;
                #pragma unroll
                for (int q = 0; q < ND; q++)
                    acc = fmaf(Hp[c3][m*11 + q], part[q*11 + l], acc);
                Hp[c3 ^ 1][tid] = acc;
            }
            c3 ^= 1;
            __syncthreads();
        }
        float sv = (tid < NB) ? __ldcg(g_sc + tid) : 0.f;
        #pragma unroll
        for (int o = 16; o; o >>= 1) sv += __shfl_xor_sync(0xffffffffu, sv, o);
        if (lane == 0) red[w] = sv;
        __syncthreads();
        if (tid == 0) {
            float tot = red[0] + red[1] + red[2] + red[3];
            for (int i = 0; i < 16; i++) tot += g_sc2[i];
            float y[ND];
            for (int m = 0; m < ND; m++) {
                float acc = 0.f;
                for (int l = 0; l < ND; l++)
                    acc = fmaf(Hp[c3][m*11 + l], g_R[l], acc);
                y[m] = acc;
            }
            float z = 0.f;
            for (int m = 0; m < ND; m++) z = fmaf(g_L[m], y[m], z);
            out[0] = logf(z) + tot;
        }
    }
}

// ============================================================
extern "C" void kernel_launch(void* const* d_in, const int* in_sizes, int n_in,
                              void* d_out, int out_size)
{
    const float* obs = (const float*)d_in[0];
    const int*   cid = (const int*)  d_in[1];
    const float* emb = (const float*)d_in[2];
    const float* ecw = (const float*)d_in[3];
    const float* ecb = (const float*)d_in[4];
    const float* elw = (const float*)d_in[5];
    const float* elb = (const float*)d_in[6];
    const float* tcw = (const float*)d_in[7];
    const float* tcb = (const float*)d_in[8];
    const float* tlw = (const float*)d_in[9];
    const float* tlb = (const float*)d_in[10];
    float* out = (float*)d_out;

    mono_kernel<<<NB, 512>>>(obs, cid, emb, ecw, ecb, elw, elb,
                             tcw, tcb, tlw, tlb, out);
}